// round 8
// baseline (speedup 1.0000x reference)
#include <cuda_runtime.h>
#include <math_constants.h>

static constexpr int   N_ATOMS = 256;
static constexpr float RCUT    = 6.0f;
static constexpr float RCUT2   = 36.0f;
static constexpr int   NFEAT   = 24;
static constexpr int   MAXA    = 512;       // max total atoms (B<=2)
static constexpr int   CCHUNK  = 592;       // 148 SMs * 4 CTAs, one wave
static constexpr int   MAXSLOT = 24;

// persistent scratch (device globals; zero-init; self-resetting)
__device__ float4       g_dA[MAXA][N_ATOMS];   // dx, dy, dz, sq
__device__ float4       g_dB[MAXA][N_ATOMS];   // fc*e^{-.01sq}, fc*e^{-.1sq}, 1/r, fc
__device__ int          g_M[MAXA];
__device__ float        g_slot[MAXA][MAXSLOT][16];
__device__ int          g_done[MAXA];

// packed f32x2 helpers (Blackwell fma.rn.f32x2)
__device__ __forceinline__ unsigned long long pk2(float lo, float hi) {
    unsigned long long d;
    asm("mov.b64 %0, {%1, %2};" : "=l"(d)
        : "r"(__float_as_uint(lo)), "r"(__float_as_uint(hi)));
    return d;
}
__device__ __forceinline__ void upk2(unsigned long long v, float& lo, float& hi) {
    unsigned int a, b;
    asm("mov.b64 {%0, %1}, %2;" : "=r"(a), "=r"(b) : "l"(v));
    lo = __uint_as_float(a); hi = __uint_as_float(b);
}
__device__ __forceinline__ unsigned long long ffma2(unsigned long long a,
                                                    unsigned long long b,
                                                    unsigned long long c) {
    unsigned long long d;
    asm("fma.rn.f32x2 %0, %1, %2, %3;" : "=l"(d) : "l"(a), "l"(b), "l"(c));
    return d;
}

// ---------------- K1: neighbor tables + radial features ----------------
__global__ __launch_bounds__(256)
void k1_build(const float* __restrict__ zn,
              const float* __restrict__ coords,
              float* __restrict__ out)
{
    const int i    = blockIdx.x;
    const int b    = blockIdx.y;
    const int q    = b * N_ATOMS + i;
    const int tid  = threadIdx.x;
    const int lane = tid & 31;
    const int wid  = tid >> 5;

    __shared__ float radw[7][8];
    __shared__ int   wcnt[8], woff[8], sM;

    const float* cb = coords + (size_t)b * N_ATOMS * 3;
    const float xi = cb[3*i+0], yi = cb[3*i+1], zi = cb[3*i+2];

    const int   j  = tid;
    const float dx = xi - cb[3*j+0];
    const float dy = yi - cb[3*j+1];
    const float dz = zi - cb[3*j+2];
    const float sq = dx*dx + dy*dy + dz*dz;
    const bool  valid = (j != i) && (sq < RCUT2);
    const float r  = sqrtf(sq);
    const float fc = valid ? 0.5f * (__cosf(CUDART_PI_F * r * (1.0f/RCUT)) + 1.0f)
                           : 0.0f;

    float g[7];
    {
        const float rm2 = r - 2.0f;
        g[0] = fc;
        g[1] = __expf(-0.1f * sq        ) * fc;
        g[2] = __expf(-1.0f * sq        ) * fc;
        g[3] = __expf(-0.1f * rm2 * rm2 ) * fc;
        g[4] = __expf(-1.0f * rm2 * rm2 ) * fc;
        g[5] = __cosf(1.0f * r) * fc;
        g[6] = __cosf(2.0f * r) * fc;
    }
#pragma unroll
    for (int f = 0; f < 7; f++) {
        float v = g[f];
#pragma unroll
        for (int s = 16; s > 0; s >>= 1) v += __shfl_down_sync(0xffffffffu, v, s);
        if (lane == 0) radw[f][wid] = v;
    }

    const unsigned bm = __ballot_sync(0xffffffffu, valid);
    const int before = __popc(bm & ((1u << lane) - 1u));
    if (lane == 0) wcnt[wid] = __popc(bm);
    __syncthreads();
    if (tid == 0) {
        int o = 0;
#pragma unroll
        for (int w = 0; w < 8; w++) { woff[w] = o; o += wcnt[w]; }
        sM = o;
    }
    __syncthreads();
    if (valid) {
        const int p = woff[wid] + before;
        g_dA[q][p] = make_float4(dx, dy, dz, sq);
        const float e01 = __expf(-0.01f * sq);
        const float e10 = __expf(-0.1f  * sq);
        g_dB[q][p] = make_float4(fc * e01, fc * e10, rsqrtf(sq), fc);
    }
    // zero angular outputs (combiner overwrites atoms that have pairs)
    if (tid >= 32 && tid < 48) out[(size_t)q * NFEAT + 8 + (tid - 32)] = 0.0f;
    if (tid == 0) {
        g_M[q] = sM;
        float* o = out + (size_t)q * NFEAT;
        o[0] = zn[i];
#pragma unroll
        for (int f = 0; f < 7; f++) {
            float s = 0.0f;
#pragma unroll
            for (int w = 0; w < 8; w++) s += radw[f][w];
            o[1 + f] = s;
        }
    }
}

// ---------------- K3': scan + equal-work angular chunks + inline combine ----------------
__global__ __launch_bounds__(256, 4)
void k3_angular(float* __restrict__ out, int A)
{
    const int c    = blockIdx.x;
    const int tid  = threadIdx.x;
    const int lane = tid & 31;
    const int wid  = tid >> 5;

    __shared__ float4       sA[N_ATOMS];
    __shared__ float4       sB[N_ATOMS];
    __shared__ unsigned int sP[MAXA + 1];      // prefix sums (sP[0]=0)
    __shared__ float        sRed[8][16];
    __shared__ int          sIsLast;

    // --- per-CTA scan of pair counts (cheap, removes separate kernel) ---
    {
        __shared__ unsigned int sv[MAXA];
        for (int t = tid; t < MAXA; t += 256) {
            unsigned int n = 0;
            if (t < A) { const int M = g_M[t]; n = (unsigned int)(M * (M - 1) / 2); }
            sv[t] = n;
        }
        __syncthreads();
        for (int off = 1; off < MAXA; off <<= 1) {
            unsigned int v0 = 0, v1 = 0;
            const int t0 = tid, t1 = tid + 256;
            if (t0 >= off) v0 = sv[t0 - off];
            if (t1 >= off) v1 = sv[t1 - off];
            __syncthreads();
            sv[t0] += v0; sv[t1] += v1;
            __syncthreads();
        }
        for (int t = tid; t < MAXA; t += 256) sP[t + 1] = sv[t];
        if (tid == 0) sP[0] = 0u;
        __syncthreads();
    }

    const unsigned long long T     = sP[MAXA];
    const unsigned long long start = ((unsigned long long)c       * T) / CCHUNK;
    const unsigned long long end   = ((unsigned long long)(c + 1) * T) / CCHUNK;
    if (start >= end) return;

    // largest a with sP[a] <= start
    int lo = 0, hi = MAXA;
    while (hi - lo > 1) {
        const int mid = (lo + hi) >> 1;
        if ((unsigned long long)sP[mid] <= start) lo = mid; else hi = mid;
    }
    int a = lo;
    unsigned long long pos = start;

    // fc(s) = fma(0.5*v, poly(v), 1), v = pi^2 s / 36  (deg-8 Taylor of cos)
    const float C1 = -0.5f;
    const float C2 =  1.0f / 24.0f;
    const float C3 = -1.0f / 720.0f;
    const float C4 =  1.0f / 40320.0f;
    const float C5 = -1.0f / 3628800.0f;
    const float C6 =  1.0f / 479001600.0f;
    const float C7 = -1.0f / 87178291200.0f;
    const float C8 =  1.0f / 20922789888000.0f;
    const float VSC = CUDART_PI_F * CUDART_PI_F / 36.0f;

    while (pos < end) {
        const unsigned int Pa  = sP[a];
        const unsigned int Pa1 = sP[a + 1];
        if ((unsigned long long)Pa1 <= pos) { a++; continue; }
        const unsigned long long seg_end =
            ((unsigned long long)Pa1 < end) ? (unsigned long long)Pa1 : end;

        const int M = g_M[a];
        for (int t = tid; t < M; t += 256) { sA[t] = g_dA[a][t]; sB[t] = g_dB[a][t]; }
        __syncthreads();

        unsigned long long acc[8];
#pragma unroll
        for (int f = 0; f < 8; f++) acc[f] = 0ull;

        const int l0 = (int)(pos - Pa);
        const int l1 = (int)(seg_end - Pa);
        for (int l = l0 + tid; l < l1; l += 256) {
            int k = (int)((sqrtf(8.0f * (float)l + 1.0f) + 1.0f) * 0.5f);
            while (k * (k - 1) / 2 > l)  k--;
            while ((k + 1) * k / 2 <= l) k++;
            const int jj = l - k * (k - 1) / 2;

            const float4 aj = sA[jj];
            const float4 ak = sA[k];
            const float4 bj = sB[jj];
            const float4 bk = sB[k];

            const float dot  = aj.x*ak.x + aj.y*ak.y + aj.z*ak.z;
            const float cth  = dot * bj.z * bk.z;
            const float sq2  = aj.w + ak.w;
            const float sqjk = fmaf(-2.0f, dot, sq2);

            const float v  = sqjk * VSC;
            float poly = fmaf(C8, v, C7);
            poly = fmaf(poly, v, C6);  poly = fmaf(poly, v, C5);
            poly = fmaf(poly, v, C4);  poly = fmaf(poly, v, C3);
            poly = fmaf(poly, v, C2);  poly = fmaf(poly, v, C1);
            float fcjk = fmaf(0.5f * v, poly, 1.0f);
            fcjk = (sqjk < RCUT2) ? fcjk : 0.0f;

            const float e2a = bj.x * bk.x;
            const float e2b = bj.y * bk.y;

            const float t   = __expf(-0.01f * sqjk);
            const float t2  = t * t, t4 = t2 * t2;
            const float t10 = t4 * t4 * t2;

            const float e3a = e2a * (t   * fcjk);
            const float e3b = e2b * (t10 * fcjk);

            const float p  = fmaxf(1.0f + cth, 0.0f);
            const float m  = fmaxf(1.0f - cth, 0.0f);
            const float p2 = p*p, p4 = p2*p2;
            const float m2 = m*m, m4 = m2*m2;

            const unsigned long long Ea = pk2(e3a, e2a);
            const unsigned long long Eb = pk2(e3b, e2b);
            const unsigned long long Mv = pk2(m,  m );
            const unsigned long long Pv = pk2(p,  p );
            const unsigned long long M4 = pk2(m4, m4);
            const unsigned long long P4 = pk2(p4, p4);

            acc[0] = ffma2(Mv, Ea, acc[0]);
            acc[1] = ffma2(Pv, Ea, acc[1]);
            acc[2] = ffma2(M4, Ea, acc[2]);
            acc[3] = ffma2(P4, Ea, acc[3]);
            acc[4] = ffma2(Mv, Eb, acc[4]);
            acc[5] = ffma2(Pv, Eb, acc[5]);
            acc[6] = ffma2(M4, Eb, acc[6]);
            acc[7] = ffma2(P4, Eb, acc[7]);
        }

        // reduce 16 features across the CTA (fixed order -> deterministic)
#pragma unroll
        for (int f = 0; f < 8; f++) {
            float v3, v2;
            upk2(acc[f], v3, v2);
#pragma unroll
            for (int s = 16; s > 0; s >>= 1) {
                v3 += __shfl_down_sync(0xffffffffu, v3, s);
                v2 += __shfl_down_sync(0xffffffffu, v2, s);
            }
            if (lane == 0) { sRed[wid][f] = v3; sRed[wid][8 + f] = v2; }
        }
        __syncthreads();

        // chunk-range bookkeeping for atom a
        const unsigned long long cf =
            ((unsigned long long)CCHUNK * (Pa + 1) + T - 1) / T - 1;   // first chunk of a
        const unsigned long long cl =
            ((unsigned long long)CCHUNK * Pa1 - 1) / T;                // last chunk of a
        int ns = (int)(cl - cf) + 1;
        if (ns > MAXSLOT) ns = MAXSLOT;

        if (tid < 16) {
            float s = 0.0f;
#pragma unroll
            for (int w = 0; w < 8; w++) s += sRed[w][tid];
            int slot = c - (int)cf;
            if (slot < 0) slot = 0;
            if (slot >= MAXSLOT) slot = MAXSLOT - 1;
            g_slot[a][slot][tid] = s;
        }
        __syncthreads();

        // last-arriving chunk combines all slots for atom a
        if (tid == 0) {
            __threadfence();
            const int old = atomicAdd(&g_done[a], 1);
            sIsLast = (old == ns - 1) ? 1 : 0;
        }
        __syncthreads();
        if (sIsLast) {
            if (tid == 0) g_done[a] = 0;          // reset for next launch/replay
            if (tid < 16) {
                __threadfence();
                float s = 0.0f;
                for (int sl = 0; sl < ns; sl++) s += __ldcg(&g_slot[a][sl][tid]);
                const float sc8[8] = {2.0f, 2.0f, 0.25f, 0.25f,
                                      2.0f, 2.0f, 0.25f, 0.25f};
                float* o = out + (size_t)a * NFEAT;
                if (tid < 8) o[8 + tid]        = s * sc8[tid];
                else         o[16 + (tid - 8)] = s * sc8[tid - 8];
            }
        }
        __syncthreads();

        pos = seg_end;
        a++;
    }
}

extern "C" void kernel_launch(void* const* d_in, const int* in_sizes, int n_in,
                              void* d_out, int out_size)
{
    const float* zn     = (const float*)d_in[0];   // atomic_numbers [N]
    const float* coords = (const float*)d_in[1];   // coordinates   [B, N, 3]
    float*       out    = (float*)d_out;           // [B, N, 24]

    const int B = in_sizes[1] / (N_ATOMS * 3);
    const int A = B * N_ATOMS;

    k1_build  <<<dim3(N_ATOMS, B), 256>>>(zn, coords, out);
    k3_angular<<<CCHUNK, 256>>>(out, A);
}

// round 10
// speedup vs baseline: 1.5644x; 1.5644x over previous
#include <cuda_runtime.h>
#include <math_constants.h>

static constexpr int   N_ATOMS = 256;
static constexpr float RCUT    = 6.0f;
static constexpr float RCUT2   = 36.0f;
static constexpr int   NFEAT   = 24;

// packed f32x2 helpers (Blackwell fma.rn.f32x2)
__device__ __forceinline__ unsigned long long pk2(float lo, float hi) {
    unsigned long long d;
    asm("mov.b64 %0, {%1, %2};" : "=l"(d)
        : "r"(__float_as_uint(lo)), "r"(__float_as_uint(hi)));
    return d;
}
__device__ __forceinline__ void upk2(unsigned long long v, float& lo, float& hi) {
    unsigned int a, b;
    asm("mov.b64 {%0, %1}, %2;" : "=r"(a), "=r"(b) : "l"(v));
    lo = __uint_as_float(a); hi = __uint_as_float(b);
}
__device__ __forceinline__ unsigned long long ffma2(unsigned long long a,
                                                    unsigned long long b,
                                                    unsigned long long c) {
    unsigned long long d;
    asm("fma.rn.f32x2 %0, %1, %2, %3;" : "=l"(d) : "l"(a), "l"(b), "l"(c));
    return d;
}

__global__ __launch_bounds__(256, 4)
void acsf_kernel(const float* __restrict__ zn,
                 const float* __restrict__ coords,
                 float* __restrict__ out)
{
    const int i    = blockIdx.x;
    const int b    = blockIdx.y;
    const int tid  = threadIdx.x;
    const int lane = tid & 31;
    const int wid  = tid >> 5;

    __shared__ float4 sA[N_ATOMS];     // dx, dy, dz, sq
    __shared__ float4 sB[N_ATOMS];     // fc*e^{-.01sq}, fc*e^{-.1sq}, 1/r, fc
    __shared__ float  radw[7][8];
    __shared__ float  angw[16][8];
    __shared__ int    wcnt[8], woff[8];
    __shared__ int    sM;

    const float* cb = coords + (size_t)b * N_ATOMS * 3;
    const float xi = cb[3*i+0], yi = cb[3*i+1], zi = cb[3*i+2];

    // ---- Phase 1: pair (i, j=tid): radial features + per-neighbor factors ----
    const int   j  = tid;
    const float dx = xi - cb[3*j+0];
    const float dy = yi - cb[3*j+1];
    const float dz = zi - cb[3*j+2];
    const float sq = dx*dx + dy*dy + dz*dz;
    const bool  valid = (j != i) && (sq < RCUT2);
    const float r  = sqrtf(sq);
    const float fc = valid ? 0.5f * (__cosf(CUDART_PI_F * r * (1.0f/RCUT)) + 1.0f)
                           : 0.0f;

    float g[7];
    {
        const float rm2 = r - 2.0f;
        g[0] = fc;
        g[1] = __expf(-0.1f * sq        ) * fc;   // (rs=0, eta=0.1)
        g[2] = __expf(-1.0f * sq        ) * fc;   // (rs=0, eta=1.0)
        g[3] = __expf(-0.1f * rm2 * rm2 ) * fc;   // (rs=2, eta=0.1)
        g[4] = __expf(-1.0f * rm2 * rm2 ) * fc;   // (rs=2, eta=1.0)
        g[5] = __cosf(1.0f * r) * fc;             // kappa=1
        g[6] = __cosf(2.0f * r) * fc;             // kappa=2
    }
#pragma unroll
    for (int f = 0; f < 7; f++) {
        float v = g[f];
#pragma unroll
        for (int s = 16; s > 0; s >>= 1) v += __shfl_down_sync(0xffffffffu, v, s);
        if (lane == 0) radw[f][wid] = v;
    }

    // ---- Phase 2: deterministic neighbor compaction (ascending j) + zero pad ----
    const unsigned bm = __ballot_sync(0xffffffffu, valid);
    const int before = __popc(bm & ((1u << lane) - 1u));
    if (lane == 0) wcnt[wid] = __popc(bm);
    __syncthreads();
    if (tid == 0) {
        int o = 0;
#pragma unroll
        for (int w = 0; w < 8; w++) { woff[w] = o; o += wcnt[w]; }
        sM = o;
    }
    __syncthreads();
    const int M = sM;
    if (valid) {
        const int p = woff[wid] + before;
        sA[p] = make_float4(dx, dy, dz, sq);
        const float e01 = __expf(-0.01f * sq);
        const float e10 = __expf(-0.1f  * sq);
        sB[p] = make_float4(fc * e01, fc * e10, rsqrtf(sq), fc);
    }
    if (tid >= M) {   // zero-pad up to 256: padded entries contribute exactly 0
        sA[tid] = make_float4(0.0f, 0.0f, 0.0f, 0.0f);
        sB[tid] = make_float4(0.0f, 0.0f, 0.0f, 0.0f);
    }
    __syncthreads();

    // ---- Phase 3: register-tiled 32x32 pair tiles, k broadcast via shfl ----
    const int nt = (M + 31) >> 5;            // 32-tiles
    const int TP = nt * (nt + 1) / 2;        // triangular tile-pairs (jt <= kt)

    unsigned long long acc[8];
#pragma unroll
    for (int f = 0; f < 8; f++) acc[f] = 0ull;

    const float PI6 = CUDART_PI_F / 6.0f;

    for (int tp = wid; tp < TP; tp += 8) {
        // decode tp -> (kt, jt), jt <= kt  (tiny ints; once per tile)
        int kt = (int)((sqrtf(8.0f * (float)tp + 1.0f) - 1.0f) * 0.5f);
        while (kt * (kt + 1) / 2 > tp)       kt--;
        while ((kt + 1) * (kt + 2) / 2 <= tp) kt++;
        const int jt = tp - kt * (kt + 1) / 2;
        const bool diag = (jt == kt);

        const float4 ck = sA[kt * 32 + lane];   // this lane's k-atom
        const float4 dk = sB[kt * 32 + lane];
        const float4 aj = sA[jt * 32 + lane];   // this lane's j-atom
        const float4 bj = sB[jt * 32 + lane];

#pragma unroll 4
        for (int s = 0; s < 32; s++) {
            const float akx = __shfl_sync(0xffffffffu, ck.x, s);
            const float aky = __shfl_sync(0xffffffffu, ck.y, s);
            const float akz = __shfl_sync(0xffffffffu, ck.z, s);
            const float akw = __shfl_sync(0xffffffffu, ck.w, s);
            const float dkx = __shfl_sync(0xffffffffu, dk.x, s);
            const float dky = __shfl_sync(0xffffffffu, dk.y, s);
            const float dkz = __shfl_sync(0xffffffffu, dk.z, s);

            const float dot  = aj.x*akx + aj.y*aky + aj.z*akz;
            const float cth  = dot * bj.z * dkz;              // cos(theta)
            const float sq2  = aj.w + akw;
            const float sqjk = fmaf(-2.0f, dot, sq2);         // |dj-dk|^2

            const float rjk  = sqrtf(fmaxf(sqjk, 0.0f));
            float fcjk = fmaf(0.5f, __cosf(rjk * PI6), 0.5f);
            fcjk = (sqjk < RCUT2) ? fcjk : 0.0f;

            float e2a = bj.x * dkx;               // e^{-.01(sqj+sqk)} fcj fck
            float e2b = bj.y * dky;               // e^{-.1 (sqj+sqk)} fcj fck
            if (diag) {                           // keep only j(=lane) < k(=s)
                const bool keep = (lane < s);
                e2a = keep ? e2a : 0.0f;
                e2b = keep ? e2b : 0.0f;
            }

            const float e3a = e2a * (__expf(-0.01f * sqjk) * fcjk);
            const float e3b = e2b * (__expf(-0.1f  * sqjk) * fcjk);

            const float p  = fmaxf(1.0f + cth, 0.0f);
            const float m  = fmaxf(1.0f - cth, 0.0f);
            const float p2 = p*p, p4 = p2*p2;
            const float m2 = m*m, m4 = m2*m2;

            const unsigned long long Ea = pk2(e3a, e2a);
            const unsigned long long Eb = pk2(e3b, e2b);
            const unsigned long long Mv = pk2(m,  m );
            const unsigned long long Pv = pk2(p,  p );
            const unsigned long long M4 = pk2(m4, m4);
            const unsigned long long P4 = pk2(p4, p4);

            acc[0] = ffma2(Mv, Ea, acc[0]);
            acc[1] = ffma2(Pv, Ea, acc[1]);
            acc[2] = ffma2(M4, Ea, acc[2]);
            acc[3] = ffma2(P4, Ea, acc[3]);
            acc[4] = ffma2(Mv, Eb, acc[4]);
            acc[5] = ffma2(Pv, Eb, acc[5]);
            acc[6] = ffma2(M4, Eb, acc[6]);
            acc[7] = ffma2(P4, Eb, acc[7]);
        }
    }

#pragma unroll
    for (int f = 0; f < 8; f++) {
        float v3, v2;
        upk2(acc[f], v3, v2);
#pragma unroll
        for (int s = 16; s > 0; s >>= 1) {
            v3 += __shfl_down_sync(0xffffffffu, v3, s);
            v2 += __shfl_down_sync(0xffffffffu, v2, s);
        }
        if (lane == 0) { angw[f][wid] = v3; angw[8 + f][wid] = v2; }
    }
    __syncthreads();

    // ---- Output: 24 features, fixed summation order ----
    if (tid == 0) {
        float* o = out + ((size_t)(b * N_ATOMS + i)) * NFEAT;
        o[0] = zn[i];
#pragma unroll
        for (int f = 0; f < 7; f++) {
            float s = 0.0f;
#pragma unroll
            for (int w = 0; w < 8; w++) s += radw[f][w];
            o[1 + f] = s;
        }
        // x2 (j<k symmetry) * 2^(1-zeta): zeta=1 -> 2, zeta=4 -> 0.25
        const float sc8[8] = {2.0f, 2.0f, 0.25f, 0.25f, 2.0f, 2.0f, 0.25f, 0.25f};
#pragma unroll
        for (int f = 0; f < 8; f++) {
            float s3 = 0.0f, s2 = 0.0f;
#pragma unroll
            for (int w = 0; w < 8; w++) { s3 += angw[f][w]; s2 += angw[8 + f][w]; }
            o[8  + f] = s3 * sc8[f];
            o[16 + f] = s2 * sc8[f];
        }
    }
}

extern "C" void kernel_launch(void* const* d_in, const int* in_sizes, int n_in,
                              void* d_out, int out_size)
{
    const float* zn     = (const float*)d_in[0];   // atomic_numbers [N]
    const float* coords = (const float*)d_in[1];   // coordinates   [B, N, 3]
    float*       out    = (float*)d_out;           // [B, N, 24]

    const int B = in_sizes[1] / (N_ATOMS * 3);
    dim3 grid(N_ATOMS, B);
    acsf_kernel<<<grid, 256>>>(zn, coords, out);
}

// round 13
// speedup vs baseline: 2.0650x; 1.3200x over previous
#include <cuda_runtime.h>
#include <math_constants.h>

static constexpr int   N_ATOMS = 256;
static constexpr float RCUT    = 6.0f;
static constexpr float RCUT2   = 36.0f;
static constexpr int   NFEAT   = 24;

// packed f32x2 helpers (Blackwell fma.rn.f32x2)
__device__ __forceinline__ unsigned long long pk2(float lo, float hi) {
    unsigned long long d;
    asm("mov.b64 %0, {%1, %2};" : "=l"(d)
        : "r"(__float_as_uint(lo)), "r"(__float_as_uint(hi)));
    return d;
}
__device__ __forceinline__ void upk2(unsigned long long v, float& lo, float& hi) {
    unsigned int a, b;
    asm("mov.b64 {%0, %1}, %2;" : "=r"(a), "=r"(b) : "l"(v));
    lo = __uint_as_float(a); hi = __uint_as_float(b);
}
__device__ __forceinline__ unsigned long long ffma2(unsigned long long a,
                                                    unsigned long long b,
                                                    unsigned long long c) {
    unsigned long long d;
    asm("fma.rn.f32x2 %0, %1, %2, %3;" : "=l"(d) : "l"(a), "l"(b), "l"(c));
    return d;
}

// one (j,k) pair contribution; j-side in (aj,bj), k-side passed as scalars
__device__ __forceinline__ void pair_step(const float4& aj, const float4& bj,
                                          float akx, float aky, float akz,
                                          float akw, float u1k, float u2k,
                                          float rik, bool keep,
                                          unsigned long long acc[8])
{
    const float dot  = aj.x*akx + aj.y*aky + aj.z*akz;
    const float cth  = dot * bj.z * rik;                  // cos(theta)
    const float sqjk = fmaf(-2.0f, dot, aj.w + akw);      // |dj-dk|^2

    const float rjk  = sqrtf(fmaxf(sqjk, 0.0f));
    float fcjk = fmaf(0.5f, __cosf(rjk * (CUDART_PI_F / 6.0f)), 0.5f);
    fcjk = (sqjk < RCUT2) ? fcjk : 0.0f;

    float e2a = bj.x * u1k;                // e^{-.01(sqj+sqk)} fcj fck
    float e2b = bj.y * u2k;                // e^{-.1 (sqj+sqk)} fcj fck
    e2a = keep ? e2a : 0.0f;
    e2b = keep ? e2b : 0.0f;

    const float e3a = e2a * (__expf(-0.01f * sqjk) * fcjk);
    const float e3b = e2b * (__expf(-0.1f  * sqjk) * fcjk);

    const float p  = fmaxf(1.0f + cth, 0.0f);
    const float m  = fmaxf(1.0f - cth, 0.0f);
    const float p2 = p*p, p4 = p2*p2;
    const float m2 = m*m, m4 = m2*m2;

    const unsigned long long Ea = pk2(e3a, e2a);
    const unsigned long long Eb = pk2(e3b, e2b);
    const unsigned long long Mv = pk2(m,  m );
    const unsigned long long Pv = pk2(p,  p );
    const unsigned long long M4 = pk2(m4, m4);
    const unsigned long long P4 = pk2(p4, p4);

    acc[0] = ffma2(Mv, Ea, acc[0]);
    acc[1] = ffma2(Pv, Ea, acc[1]);
    acc[2] = ffma2(M4, Ea, acc[2]);
    acc[3] = ffma2(P4, Ea, acc[3]);
    acc[4] = ffma2(Mv, Eb, acc[4]);
    acc[5] = ffma2(Pv, Eb, acc[5]);
    acc[6] = ffma2(M4, Eb, acc[6]);
    acc[7] = ffma2(P4, Eb, acc[7]);
}

__global__ __launch_bounds__(256, 4)
void acsf_kernel(const float* __restrict__ zn,
                 const float* __restrict__ coords,
                 float* __restrict__ out)
{
    const int i    = blockIdx.x;
    const int b    = blockIdx.y;
    const int tid  = threadIdx.x;
    const int lane = tid & 31;
    const int wid  = tid >> 5;

    __shared__ float4 sA[N_ATOMS];     // dx, dy, dz, sq
    __shared__ float4 sB[N_ATOMS];     // fc*e^{-.01sq}, fc*e^{-.1sq}, 1/r, fc
    __shared__ float  radw[7][8];
    __shared__ float  angw[16][8];
    __shared__ int    wcnt[8], woff[8];
    __shared__ int    sM;

    const float* cb = coords + (size_t)b * N_ATOMS * 3;
    const float xi = cb[3*i+0], yi = cb[3*i+1], zi = cb[3*i+2];

    // ---- Phase 1: pair (i, j=tid): radial features + per-neighbor factors ----
    const int   j  = tid;
    const float dx = xi - cb[3*j+0];
    const float dy = yi - cb[3*j+1];
    const float dz = zi - cb[3*j+2];
    const float sq = dx*dx + dy*dy + dz*dz;
    const bool  valid = (j != i) && (sq < RCUT2);
    const float r  = sqrtf(sq);
    const float fc = valid ? 0.5f * (__cosf(CUDART_PI_F * r * (1.0f/RCUT)) + 1.0f)
                           : 0.0f;

    float g[7];
    {
        const float rm2 = r - 2.0f;
        g[0] = fc;
        g[1] = __expf(-0.1f * sq        ) * fc;   // (rs=0, eta=0.1)
        g[2] = __expf(-1.0f * sq        ) * fc;   // (rs=0, eta=1.0)
        g[3] = __expf(-0.1f * rm2 * rm2 ) * fc;   // (rs=2, eta=0.1)
        g[4] = __expf(-1.0f * rm2 * rm2 ) * fc;   // (rs=2, eta=1.0)
        g[5] = __cosf(1.0f * r) * fc;             // kappa=1
        g[6] = __cosf(2.0f * r) * fc;             // kappa=2
    }
#pragma unroll
    for (int f = 0; f < 7; f++) {
        float v = g[f];
#pragma unroll
        for (int s = 16; s > 0; s >>= 1) v += __shfl_down_sync(0xffffffffu, v, s);
        if (lane == 0) radw[f][wid] = v;
    }

    // ---- Phase 2: deterministic neighbor compaction (ascending j) + zero pad ----
    const unsigned bm = __ballot_sync(0xffffffffu, valid);
    const int before = __popc(bm & ((1u << lane) - 1u));
    if (lane == 0) wcnt[wid] = __popc(bm);
    __syncthreads();
    if (tid == 0) {
        int o = 0;
#pragma unroll
        for (int w = 0; w < 8; w++) { woff[w] = o; o += wcnt[w]; }
        sM = o;
    }
    __syncthreads();
    const int M = sM;
    if (valid) {
        const int p = woff[wid] + before;
        sA[p] = make_float4(dx, dy, dz, sq);
        const float e01 = __expf(-0.01f * sq);
        const float e10 = __expf(-0.1f  * sq);
        sB[p] = make_float4(fc * e01, fc * e10, rsqrtf(sq), fc);
    }
    if (tid >= M) {   // zero-pad: padded entries contribute exactly 0
        sA[tid] = make_float4(0.0f, 0.0f, 0.0f, 0.0f);
        sB[tid] = make_float4(0.0f, 0.0f, 0.0f, 0.0f);
    }
    __syncthreads();

    // ---- Phase 3: all warps cooperate on every 32x32 tile (s-step split) ----
    const int nt = (M + 31) >> 5;

    unsigned long long acc[8];
#pragma unroll
    for (int f = 0; f < 8; f++) acc[f] = 0ull;

    for (int kt = 0; kt < nt; kt++) {
        const float4 ck = sA[(kt << 5) + lane];
        const float4 dk = sB[(kt << 5) + lane];

        // diagonal tile: cyclic pairing (lane, lane+s), s=1..16, no idle lanes
#pragma unroll
        for (int u = 0; u < 2; u++) {
            const int s   = 1 + wid + (u << 3);          // 1..16
            const int src = (lane + s) & 31;
            const float akx = __shfl_sync(0xffffffffu, ck.x, src);
            const float aky = __shfl_sync(0xffffffffu, ck.y, src);
            const float akz = __shfl_sync(0xffffffffu, ck.z, src);
            const float akw = __shfl_sync(0xffffffffu, ck.w, src);
            const float u1k = __shfl_sync(0xffffffffu, dk.x, src);
            const float u2k = __shfl_sync(0xffffffffu, dk.y, src);
            const float rik = __shfl_sync(0xffffffffu, dk.z, src);
            const bool keep = (s < 16) || (lane < 16);   // antipodal pairs once
            pair_step(ck, dk, akx, aky, akz, akw, u1k, u2k, rik, keep, acc);
        }

        // off-diagonal tiles jt < kt: k-tile regs persist, j reloaded per tile
        for (int jt = 0; jt < kt; jt++) {
            const float4 aj = sA[(jt << 5) + lane];
            const float4 bj = sB[(jt << 5) + lane];
#pragma unroll
            for (int u = 0; u < 4; u++) {
                const int s = wid + (u << 3);            // 0..31
                const float akx = __shfl_sync(0xffffffffu, ck.x, s);
                const float aky = __shfl_sync(0xffffffffu, ck.y, s);
                const float akz = __shfl_sync(0xffffffffu, ck.z, s);
                const float akw = __shfl_sync(0xffffffffu, ck.w, s);
                const float u1k = __shfl_sync(0xffffffffu, dk.x, s);
                const float u2k = __shfl_sync(0xffffffffu, dk.y, s);
                const float rik = __shfl_sync(0xffffffffu, dk.z, s);
                pair_step(aj, bj, akx, aky, akz, akw, u1k, u2k, rik, true, acc);
            }
        }
    }

#pragma unroll
    for (int f = 0; f < 8; f++) {
        float v3, v2;
        upk2(acc[f], v3, v2);
#pragma unroll
        for (int s = 16; s > 0; s >>= 1) {
            v3 += __shfl_down_sync(0xffffffffu, v3, s);
            v2 += __shfl_down_sync(0xffffffffu, v2, s);
        }
        if (lane == 0) { angw[f][wid] = v3; angw[8 + f][wid] = v2; }
    }
    __syncthreads();

    // ---- Output: 24 features, fixed summation order ----
    if (tid == 0) {
        float* o = out + ((size_t)(b * N_ATOMS + i)) * NFEAT;
        o[0] = zn[i];
#pragma unroll
        for (int f = 0; f < 7; f++) {
            float s = 0.0f;
#pragma unroll
            for (int w = 0; w < 8; w++) s += radw[f][w];
            o[1 + f] = s;
        }
        // x2 (j<k symmetry) * 2^(1-zeta): zeta=1 -> 2, zeta=4 -> 0.25
        const float sc8[8] = {2.0f, 2.0f, 0.25f, 0.25f, 2.0f, 2.0f, 0.25f, 0.25f};
#pragma unroll
        for (int f = 0; f < 8; f++) {
            float s3 = 0.0f, s2 = 0.0f;
#pragma unroll
            for (int w = 0; w < 8; w++) { s3 += angw[f][w]; s2 += angw[8 + f][w]; }
            o[8  + f] = s3 * sc8[f];
            o[16 + f] = s2 * sc8[f];
        }
    }
}

extern "C" void kernel_launch(void* const* d_in, const int* in_sizes, int n_in,
                              void* d_out, int out_size)
{
    const float* zn     = (const float*)d_in[0];   // atomic_numbers [N]
    const float* coords = (const float*)d_in[1];   // coordinates   [B, N, 3]
    float*       out    = (float*)d_out;           // [B, N, 24]

    const int B = in_sizes[1] / (N_ATOMS * 3);
    dim3 grid(N_ATOMS, B);
    acsf_kernel<<<grid, 256>>>(zn, coords, out);
}

// round 17
// speedup vs baseline: 2.3510x; 1.1385x over previous
#include <cuda_runtime.h>
#include <math_constants.h>

static constexpr int   N_ATOMS = 256;
static constexpr float RCUT    = 6.0f;
static constexpr float RCUT2   = 36.0f;
static constexpr int   NFEAT   = 24;

// one (j,k) pair contribution; j-side in (aj,bj), k-side passed as scalars
__device__ __forceinline__ void pair_step(const float4& aj, const float4& bj,
                                          float akx, float aky, float akz,
                                          float akw, float u1k, float u2k,
                                          float rik, bool keep,
                                          float acc[16])
{
    const float dot  = aj.x*akx + aj.y*aky + aj.z*akz;
    const float cth  = dot * (bj.z * rik);                // cos(theta)
    const float sqjk = fmaf(-2.0f, dot, aj.w + akw);      // |dj-dk|^2

    const float rjk  = sqrtf(fmaxf(sqjk, 0.0f));
    float fcjk = fmaf(0.5f, __cosf(rjk * (CUDART_PI_F / 6.0f)), 0.5f);
    fcjk = (sqjk < RCUT2) ? fcjk : 0.0f;

    float e2a = bj.x * u1k;                // e^{-.01(sqj+sqk)} fcj fck
    float e2b = bj.y * u2k;                // e^{-.1 (sqj+sqk)} fcj fck
    if (!keep) { e2a = 0.0f; e2b = 0.0f; }

    const float t   = __expf(-0.01f * sqjk);
    const float t2  = t * t, t4 = t2 * t2;
    const float t10 = t4 * t4 * t2;                       // e^{-.1 sqjk}

    const float e3a = e2a * (t   * fcjk);
    const float e3b = e2b * (t10 * fcjk);

    const float p  = fmaxf(1.0f + cth, 0.0f);
    const float m  = fmaxf(1.0f - cth, 0.0f);
    const float p2 = p*p, p4 = p2*p2;
    const float m2 = m*m, m4 = m2*m2;

    acc[0]  += m  * e3a;  acc[1]  += p  * e3a;
    acc[2]  += m4 * e3a;  acc[3]  += p4 * e3a;
    acc[4]  += m  * e3b;  acc[5]  += p  * e3b;
    acc[6]  += m4 * e3b;  acc[7]  += p4 * e3b;
    acc[8]  += m  * e2a;  acc[9]  += p  * e2a;
    acc[10] += m4 * e2a;  acc[11] += p4 * e2a;
    acc[12] += m  * e2b;  acc[13] += p  * e2b;
    acc[14] += m4 * e2b;  acc[15] += p4 * e2b;
}

__global__ __launch_bounds__(256, 4)
void acsf_kernel(const float* __restrict__ zn,
                 const float* __restrict__ coords,
                 float* __restrict__ out)
{
    const int i    = blockIdx.x;
    const int b    = blockIdx.y;
    const int tid  = threadIdx.x;
    const int lane = tid & 31;
    const int wid  = tid >> 5;

    __shared__ float4 sA[N_ATOMS];     // dx, dy, dz, sq
    __shared__ float4 sB[N_ATOMS];     // fc*e^{-.01sq}, fc*e^{-.1sq}, 1/r, fc
    __shared__ float  radw[7][8];
    __shared__ float  angw[16][8];
    __shared__ int    wcnt[8], woff[8];
    __shared__ int    sM;

    const float* cb = coords + (size_t)b * N_ATOMS * 3;
    const float xi = cb[3*i+0], yi = cb[3*i+1], zi = cb[3*i+2];

    // ---- Phase 1: pair (i, j=tid): radial features + per-neighbor factors ----
    const int   j  = tid;
    const float dx = xi - cb[3*j+0];
    const float dy = yi - cb[3*j+1];
    const float dz = zi - cb[3*j+2];
    const float sq = dx*dx + dy*dy + dz*dz;
    const bool  valid = (j != i) && (sq < RCUT2);
    const float r  = sqrtf(sq);
    const float fc = valid ? 0.5f * (__cosf(CUDART_PI_F * r * (1.0f/RCUT)) + 1.0f)
                           : 0.0f;

    float g[7];
    {
        const float rm2 = r - 2.0f;
        g[0] = fc;
        g[1] = __expf(-0.1f * sq        ) * fc;   // (rs=0, eta=0.1)
        g[2] = __expf(-1.0f * sq        ) * fc;   // (rs=0, eta=1.0)
        g[3] = __expf(-0.1f * rm2 * rm2 ) * fc;   // (rs=2, eta=0.1)
        g[4] = __expf(-1.0f * rm2 * rm2 ) * fc;   // (rs=2, eta=1.0)
        g[5] = __cosf(1.0f * r) * fc;             // kappa=1
        g[6] = __cosf(2.0f * r) * fc;             // kappa=2
    }
#pragma unroll
    for (int f = 0; f < 7; f++) {
        float v = g[f];
#pragma unroll
        for (int s = 16; s > 0; s >>= 1) v += __shfl_down_sync(0xffffffffu, v, s);
        if (lane == 0) radw[f][wid] = v;
    }

    // ---- Phase 2: deterministic neighbor compaction (ascending j) + zero pad ----
    const unsigned bm = __ballot_sync(0xffffffffu, valid);
    const int before = __popc(bm & ((1u << lane) - 1u));
    if (lane == 0) wcnt[wid] = __popc(bm);
    __syncthreads();
    if (tid == 0) {
        int o = 0;
#pragma unroll
        for (int w = 0; w < 8; w++) { woff[w] = o; o += wcnt[w]; }
        sM = o;
    }
    __syncthreads();
    const int M = sM;
    if (valid) {
        const int p = woff[wid] + before;
        sA[p] = make_float4(dx, dy, dz, sq);
        const float e01 = __expf(-0.01f * sq);
        const float e10 = __expf(-0.1f  * sq);
        sB[p] = make_float4(fc * e01, fc * e10, rsqrtf(sq), fc);
    }
    if (tid >= M) {   // zero-pad: padded entries contribute exactly 0
        sA[tid] = make_float4(0.0f, 0.0f, 0.0f, 0.0f);
        sB[tid] = make_float4(0.0f, 0.0f, 0.0f, 0.0f);
    }
    __syncthreads();

    // ---- Phase 3: cooperative 32x32 tiles with tail-aware s-limits ----
    const int nt = (M + 31) >> 5;

    float acc[16];
#pragma unroll
    for (int f = 0; f < 16; f++) acc[f] = 0.0f;

    for (int kt = 0; kt < nt; kt++) {
        const int Mk = min(32, M - (kt << 5));      // valid k's in this tile
        const float4 ck = sA[(kt << 5) + lane];
        const float4 dk = sB[(kt << 5) + lane];

        // --- diagonal tile: cyclic pairing (lane, lane+s), s = 1..min(16,Mk-1) ---
        if (Mk == 32) {
#pragma unroll
            for (int u = 0; u < 2; u++) {
                const int s   = 1 + wid + (u << 3);          // 1..16
                const int src = (lane + s) & 31;
                const float akx = __shfl_sync(0xffffffffu, ck.x, src);
                const float aky = __shfl_sync(0xffffffffu, ck.y, src);
                const float akz = __shfl_sync(0xffffffffu, ck.z, src);
                const float akw = __shfl_sync(0xffffffffu, ck.w, src);
                const float u1k = __shfl_sync(0xffffffffu, dk.x, src);
                const float u2k = __shfl_sync(0xffffffffu, dk.y, src);
                const float rik = __shfl_sync(0xffffffffu, dk.z, src);
                const bool keep = (s < 16) || (lane < 16);   // antipodal once
                pair_step(ck, dk, akx, aky, akz, akw, u1k, u2k, rik, keep, acc);
            }
        } else {
            const int Ld = (Mk - 1 < 16) ? (Mk - 1) : 16;
            for (int s = 1 + wid; s <= Ld; s += 8) {
                const int src = (lane + s) & 31;
                const float akx = __shfl_sync(0xffffffffu, ck.x, src);
                const float aky = __shfl_sync(0xffffffffu, ck.y, src);
                const float akz = __shfl_sync(0xffffffffu, ck.z, src);
                const float akw = __shfl_sync(0xffffffffu, ck.w, src);
                const float u1k = __shfl_sync(0xffffffffu, dk.x, src);
                const float u2k = __shfl_sync(0xffffffffu, dk.y, src);
                const float rik = __shfl_sync(0xffffffffu, dk.z, src);
                const bool keep = (s < 16) || (lane < 16);
                pair_step(ck, dk, akx, aky, akz, akw, u1k, u2k, rik, keep, acc);
            }
        }

        // --- off-diagonal tiles jt < kt: broadcast k = kt*32+s, s < Mk ---
        for (int jt = 0; jt < kt; jt++) {
            const float4 aj = sA[(jt << 5) + lane];
            const float4 bj = sB[(jt << 5) + lane];
            if (Mk == 32) {
#pragma unroll
                for (int u = 0; u < 4; u++) {
                    const int s = wid + (u << 3);            // 0..31
                    const float akx = __shfl_sync(0xffffffffu, ck.x, s);
                    const float aky = __shfl_sync(0xffffffffu, ck.y, s);
                    const float akz = __shfl_sync(0xffffffffu, ck.z, s);
                    const float akw = __shfl_sync(0xffffffffu, ck.w, s);
                    const float u1k = __shfl_sync(0xffffffffu, dk.x, s);
                    const float u2k = __shfl_sync(0xffffffffu, dk.y, s);
                    const float rik = __shfl_sync(0xffffffffu, dk.z, s);
                    pair_step(aj, bj, akx, aky, akz, akw, u1k, u2k, rik, true, acc);
                }
            } else {
                for (int s = wid; s < Mk; s += 8) {
                    const float akx = __shfl_sync(0xffffffffu, ck.x, s);
                    const float aky = __shfl_sync(0xffffffffu, ck.y, s);
                    const float akz = __shfl_sync(0xffffffffu, ck.z, s);
                    const float akw = __shfl_sync(0xffffffffu, ck.w, s);
                    const float u1k = __shfl_sync(0xffffffffu, dk.x, s);
                    const float u2k = __shfl_sync(0xffffffffu, dk.y, s);
                    const float rik = __shfl_sync(0xffffffffu, dk.z, s);
                    pair_step(aj, bj, akx, aky, akz, akw, u1k, u2k, rik, true, acc);
                }
            }
        }
    }

#pragma unroll
    for (int f = 0; f < 16; f++) {
        float v = acc[f];
#pragma unroll
        for (int s = 16; s > 0; s >>= 1) v += __shfl_down_sync(0xffffffffu, v, s);
        if (lane == 0) angw[f][wid] = v;
    }
    __syncthreads();

    // ---- Output: 24 features, fixed summation order ----
    if (tid == 0) {
        float* o = out + ((size_t)(b * N_ATOMS + i)) * NFEAT;
        o[0] = zn[i];
#pragma unroll
        for (int f = 0; f < 7; f++) {
            float s = 0.0f;
#pragma unroll
            for (int w = 0; w < 8; w++) s += radw[f][w];
            o[1 + f] = s;
        }
        // x2 (j<k symmetry) * 2^(1-zeta): zeta=1 -> 2, zeta=4 -> 0.25
        const float sc8[8] = {2.0f, 2.0f, 0.25f, 0.25f, 2.0f, 2.0f, 0.25f, 0.25f};
#pragma unroll
        for (int f = 0; f < 8; f++) {
            float s3 = 0.0f, s2 = 0.0f;
#pragma unroll
            for (int w = 0; w < 8; w++) { s3 += angw[f][w]; s2 += angw[8 + f][w]; }
            o[8  + f] = s3 * sc8[f];
            o[16 + f] = s2 * sc8[f];
        }
    }
}

extern "C" void kernel_launch(void* const* d_in, const int* in_sizes, int n_in,
                              void* d_out, int out_size)
{
    const float* zn     = (const float*)d_in[0];   // atomic_numbers [N]
    const float* coords = (const float*)d_in[1];   // coordinates   [B, N, 3]
    float*       out    = (float*)d_out;           // [B, N, 24]

    const int B = in_sizes[1] / (N_ATOMS * 3);
    dim3 grid(N_ATOMS, B);
    acsf_kernel<<<grid, 256>>>(zn, coords, out);
}